// round 1
// baseline (speedup 1.0000x reference)
#include <cuda_runtime.h>
#include <cstdint>
#include <cstddef>

// ---------------------------------------------------------------------------
// TargetCentricAttention: B=4, S=2048, D=1024, fp32 in/out.
//   q = x @ Wq^T + bq ; k = x @ Wk^T + bk ; v = x @ Wv^T + bv
//   scores = q @ k^T / sqrt(D) ; w = softmax(scores, axis=k)
//   out[b,k,d] = sum_q w[b,q,k] * v[b,q,d]        (transposed aggregation)
//
// Round-0 implementation: tf32 mma.sync (m16n8k8) tiled GEMMs, fp32 softmax.
// ---------------------------------------------------------------------------

namespace {
constexpr int BATCH = 4;
constexpr int SEQ   = 2048;
constexpr int DIM   = 1024;
constexpr int MTOK  = BATCH * SEQ;   // 8192 tokens

constexpr int BM = 128, BN = 128, BK = 32;
constexpr int BMp = BM + 4;          // smem padding: breaks quad bank conflicts
constexpr int BNp = BN + 4;
constexpr int NTHREADS = 256;        // 8 warps: 4 (M) x 2 (N)
}

// Scratch (allocation-free rule: __device__ globals)
__device__ float g_q[(size_t)MTOK * DIM];            // 32 MB
__device__ float g_k[(size_t)MTOK * DIM];            // 32 MB
__device__ float g_v[(size_t)MTOK * DIM];            // 32 MB
__device__ float g_w[(size_t)BATCH * SEQ * SEQ];     // 64 MB softmax weights

// Round-to-nearest tf32 (unbiased — truncation would bias ~1e-3 coherently)
__device__ __forceinline__ uint32_t f2tf32(float x) {
    uint32_t u;
    asm("cvt.rna.tf32.f32 %0, %1;" : "=r"(u) : "f"(x));
    return u;
}

__device__ __forceinline__ void mma_tf32(float c[4],
                                         uint32_t a0, uint32_t a1, uint32_t a2, uint32_t a3,
                                         uint32_t b0, uint32_t b1) {
    asm volatile(
        "mma.sync.aligned.m16n8k8.row.col.f32.tf32.tf32.f32 "
        "{%0,%1,%2,%3}, {%4,%5,%6,%7}, {%8,%9}, {%0,%1,%2,%3};"
        : "+f"(c[0]), "+f"(c[1]), "+f"(c[2]), "+f"(c[3])
        : "r"(a0), "r"(a1), "r"(a2), "r"(a3), "r"(b0), "r"(b1));
}

// ---------------------------------------------------------------------------
// Shared GEMM core: C[m,n] = alpha * sum_k A_log[m,k] * B_log[k,n]  (+ bias[n])
//   ALAY==0 : A_log[m,k] = A[m*lda + k]   (row-major, K contiguous)
//   ALAY==1 : A_log[m,k] = A[k*lda + m]   (K-outer; used for Wts^T)
//   BLAY==0 : B_log[k,n] = B[n*ldb + k]   (i.e. "B^T", K contiguous)
//   BLAY==1 : B_log[k,n] = B[k*ldb + n]   (row-major)
// Tile 128x128x32, 256 threads. All problem dims are multiples of the tiles.
// ---------------------------------------------------------------------------
template <int ALAY, int BLAY>
__device__ __forceinline__ void gemm_core(const float* __restrict__ A,
                                          const float* __restrict__ Bmat,
                                          float* __restrict__ C,
                                          int Kdim, int lda, int ldb, int ldc,
                                          float alpha, const float* __restrict__ bias) {
    __shared__ uint32_t As[BK][BMp];   // stored [k][m], tf32-rounded bits
    __shared__ uint32_t Bs[BK][BNp];   // stored [k][n]

    const int tid  = threadIdx.x;
    const int lane = tid & 31;
    const int warp = tid >> 5;
    const int wm   = (warp & 3) * 32;  // warp M offset within block tile
    const int wn   = (warp >> 2) * 64; // warp N offset
    const int mBase = blockIdx.y * BM;
    const int nBase = blockIdx.x * BN;

    float acc[2][8][4];
#pragma unroll
    for (int i = 0; i < 2; i++)
#pragma unroll
        for (int j = 0; j < 8; j++)
#pragma unroll
            for (int t = 0; t < 4; t++) acc[i][j][t] = 0.0f;

    for (int kt = 0; kt < Kdim; kt += BK) {
        // ---- stage A tile ----
        if (ALAY == 0) {
#pragma unroll
            for (int i = 0; i < 4; i++) {
                int idx4 = tid + i * NTHREADS;      // 1024 float4 = 128x32
                int row  = idx4 >> 3;               // m within tile (8 float4/row)
                int c4   = idx4 & 7;
                float4 va = *reinterpret_cast<const float4*>(
                    &A[(size_t)(mBase + row) * lda + kt + c4 * 4]);
                As[c4 * 4 + 0][row] = f2tf32(va.x);
                As[c4 * 4 + 1][row] = f2tf32(va.y);
                As[c4 * 4 + 2][row] = f2tf32(va.z);
                As[c4 * 4 + 3][row] = f2tf32(va.w);
            }
        } else {
#pragma unroll
            for (int i = 0; i < 4; i++) {
                int idx4 = tid + i * NTHREADS;
                int rk   = idx4 >> 5;               // k within tile (32 float4/row)
                int c4   = idx4 & 31;
                float4 va = *reinterpret_cast<const float4*>(
                    &A[(size_t)(kt + rk) * lda + mBase + c4 * 4]);
                As[rk][c4 * 4 + 0] = f2tf32(va.x);
                As[rk][c4 * 4 + 1] = f2tf32(va.y);
                As[rk][c4 * 4 + 2] = f2tf32(va.z);
                As[rk][c4 * 4 + 3] = f2tf32(va.w);
            }
        }
        // ---- stage B tile ----
        if (BLAY == 0) {
#pragma unroll
            for (int i = 0; i < 4; i++) {
                int idx4 = tid + i * NTHREADS;
                int rown = idx4 >> 3;
                int c4   = idx4 & 7;
                float4 vb = *reinterpret_cast<const float4*>(
                    &Bmat[(size_t)(nBase + rown) * ldb + kt + c4 * 4]);
                Bs[c4 * 4 + 0][rown] = f2tf32(vb.x);
                Bs[c4 * 4 + 1][rown] = f2tf32(vb.y);
                Bs[c4 * 4 + 2][rown] = f2tf32(vb.z);
                Bs[c4 * 4 + 3][rown] = f2tf32(vb.w);
            }
        } else {
#pragma unroll
            for (int i = 0; i < 4; i++) {
                int idx4 = tid + i * NTHREADS;
                int rk   = idx4 >> 5;
                int c4   = idx4 & 31;
                float4 vb = *reinterpret_cast<const float4*>(
                    &Bmat[(size_t)(kt + rk) * ldb + nBase + c4 * 4]);
                Bs[rk][c4 * 4 + 0] = f2tf32(vb.x);
                Bs[rk][c4 * 4 + 1] = f2tf32(vb.y);
                Bs[rk][c4 * 4 + 2] = f2tf32(vb.z);
                Bs[rk][c4 * 4 + 3] = f2tf32(vb.w);
            }
        }
        __syncthreads();

        // ---- compute: 4 k-steps of 8 ----
#pragma unroll
        for (int ks = 0; ks < 4; ks++) {
            const int kb = ks * 8;
            uint32_t af[2][4];
#pragma unroll
            for (int mi = 0; mi < 2; mi++) {
                int m0 = wm + mi * 16 + (lane >> 2);
                af[mi][0] = As[kb + (lane & 3)][m0];
                af[mi][1] = As[kb + (lane & 3)][m0 + 8];
                af[mi][2] = As[kb + (lane & 3) + 4][m0];
                af[mi][3] = As[kb + (lane & 3) + 4][m0 + 8];
            }
#pragma unroll
            for (int ni = 0; ni < 8; ni++) {
                int n0 = wn + ni * 8 + (lane >> 2);
                uint32_t b0 = Bs[kb + (lane & 3)][n0];
                uint32_t b1 = Bs[kb + (lane & 3) + 4][n0];
#pragma unroll
                for (int mi = 0; mi < 2; mi++)
                    mma_tf32(acc[mi][ni], af[mi][0], af[mi][1], af[mi][2], af[mi][3], b0, b1);
            }
        }
        __syncthreads();
    }

    // ---- epilogue ----
#pragma unroll
    for (int mi = 0; mi < 2; mi++) {
#pragma unroll
        for (int ni = 0; ni < 8; ni++) {
            int row = mBase + wm + mi * 16 + (lane >> 2);
            int col = nBase + wn + ni * 8 + (lane & 3) * 2;
            float b0v = bias ? bias[col] : 0.0f;
            float b1v = bias ? bias[col + 1] : 0.0f;
            C[(size_t)row * ldc + col]           = alpha * acc[mi][ni][0] + b0v;
            C[(size_t)row * ldc + col + 1]       = alpha * acc[mi][ni][1] + b1v;
            C[(size_t)(row + 8) * ldc + col]     = alpha * acc[mi][ni][2] + b0v;
            C[(size_t)(row + 8) * ldc + col + 1] = alpha * acc[mi][ni][3] + b1v;
        }
    }
}

// ---------------------------------------------------------------------------
// Kernel wrappers
// ---------------------------------------------------------------------------

// QKV projection: y = x @ W^T + b. blockIdx.z selects {q,k,v}.
__global__ void __launch_bounds__(NTHREADS) qkv_kernel(
    const float* __restrict__ x,
    const float* __restrict__ Wq, const float* __restrict__ bq,
    const float* __restrict__ Wk, const float* __restrict__ bk,
    const float* __restrict__ Wv, const float* __restrict__ bv) {
    const float* W;
    const float* bias;
    float* out;
    if (blockIdx.z == 0)      { W = Wq; bias = bq; out = g_q; }
    else if (blockIdx.z == 1) { W = Wk; bias = bk; out = g_k; }
    else                      { W = Wv; bias = bv; out = g_v; }
    gemm_core<0, 0>(x, W, out, DIM, DIM, DIM, DIM, 1.0f, bias);
}

// scores[b,q,k] = (q . k) / 32   (sqrt(1024) = 32 exactly)
__global__ void __launch_bounds__(NTHREADS) scores_kernel() {
    int b = blockIdx.z;
    gemm_core<0, 0>(g_q + (size_t)b * SEQ * DIM,
                    g_k + (size_t)b * SEQ * DIM,
                    g_w + (size_t)b * SEQ * SEQ,
                    DIM, DIM, DIM, SEQ, 0.03125f, nullptr);
}

// In-place row softmax over the key dimension (rows of length SEQ=2048).
__global__ void __launch_bounds__(256) softmax_kernel() {
    __shared__ float red[8];
    float* p = g_w + (size_t)blockIdx.x * SEQ;
    const int tid = threadIdx.x;

    float4 v0 = *reinterpret_cast<const float4*>(p + tid * 8);
    float4 v1 = *reinterpret_cast<const float4*>(p + tid * 8 + 4);

    float m = fmaxf(fmaxf(fmaxf(v0.x, v0.y), fmaxf(v0.z, v0.w)),
                    fmaxf(fmaxf(v1.x, v1.y), fmaxf(v1.z, v1.w)));
#pragma unroll
    for (int o = 16; o > 0; o >>= 1) m = fmaxf(m, __shfl_xor_sync(0xffffffffu, m, o));
    if ((tid & 31) == 0) red[tid >> 5] = m;
    __syncthreads();
    m = red[0];
#pragma unroll
    for (int i = 1; i < 8; i++) m = fmaxf(m, red[i]);
    __syncthreads();  // before red[] is reused for the sum

    v0.x = __expf(v0.x - m); v0.y = __expf(v0.y - m);
    v0.z = __expf(v0.z - m); v0.w = __expf(v0.w - m);
    v1.x = __expf(v1.x - m); v1.y = __expf(v1.y - m);
    v1.z = __expf(v1.z - m); v1.w = __expf(v1.w - m);

    float s = v0.x + v0.y + v0.z + v0.w + v1.x + v1.y + v1.z + v1.w;
#pragma unroll
    for (int o = 16; o > 0; o >>= 1) s += __shfl_xor_sync(0xffffffffu, s, o);
    if ((tid & 31) == 0) red[tid >> 5] = s;
    __syncthreads();
    float tot = red[0];
#pragma unroll
    for (int i = 1; i < 8; i++) tot += red[i];

    float inv = 1.0f / tot;
    v0.x *= inv; v0.y *= inv; v0.z *= inv; v0.w *= inv;
    v1.x *= inv; v1.y *= inv; v1.z *= inv; v1.w *= inv;
    *reinterpret_cast<float4*>(p + tid * 8)     = v0;
    *reinterpret_cast<float4*>(p + tid * 8 + 4) = v1;
}

// out[b,k,d] = sum_q Wts[b,q,k] * V[b,q,d]  =  Wts^T @ V per batch.
// A_log[m=k, kk=q] = Wts[q*SEQ + m]  -> ALAY=1, lda=SEQ
// B_log[kk=q, n=d] = V[q*DIM + n]    -> BLAY=1, ldb=DIM
__global__ void __launch_bounds__(NTHREADS) out_kernel(float* __restrict__ out) {
    int b = blockIdx.z;
    gemm_core<1, 1>(g_w + (size_t)b * SEQ * SEQ,
                    g_v + (size_t)b * SEQ * DIM,
                    out + (size_t)b * SEQ * DIM,
                    SEQ, SEQ, DIM, DIM, 1.0f, nullptr);
}

// ---------------------------------------------------------------------------

extern "C" void kernel_launch(void* const* d_in, const int* in_sizes, int n_in,
                              void* d_out, int out_size) {
    (void)in_sizes; (void)n_in; (void)out_size;
    const float* x  = (const float*)d_in[0];
    const float* Wq = (const float*)d_in[1];
    const float* bq = (const float*)d_in[2];
    const float* Wk = (const float*)d_in[3];
    const float* bk = (const float*)d_in[4];
    const float* Wv = (const float*)d_in[5];
    const float* bv = (const float*)d_in[6];
    float* out = (float*)d_out;

    dim3 blk(NTHREADS);
    qkv_kernel<<<dim3(DIM / BN, MTOK / BM, 3), blk>>>(x, Wq, bq, Wk, bk, Wv, bv);
    scores_kernel<<<dim3(SEQ / BN, SEQ / BM, BATCH), blk>>>();
    softmax_kernel<<<dim3(BATCH * SEQ), dim3(256)>>>();
    out_kernel<<<dim3(DIM / BN, SEQ / BM, BATCH), blk>>>(out);
}